// round 14
// baseline (speedup 1.0000x reference)
#include <cuda_runtime.h>
#include <cuda_fp16.h>
#include <math.h>
#include <stdint.h>

// ---------------- problem constants ----------------
#define S_     8
#define B_     128
#define N_     32
#define D_     1024
#define HEADS_ 16
#define DH_    64
#define Q_     64
#define INNER_ 1024
#define KVW_   2048
#define FFH_   4096
#define FF2_   8192
#define ROWS_  (S_*N_*Q_)    // 16384
#define KVROWS_ (S_*N_*B_)   // 32768

// ---------------- scratch ----------------
__device__ __half g_atth[(size_t)ROWS_*INNER_];
__device__ __half g_xa [(size_t)KVROWS_*D_];
__device__ __half g_wkt[(size_t)KVW_*D_];
__device__ __half g_w1t[(size_t)FF2_*INNER_];
__device__ __half g_w2t[(size_t)INNER_*FFH_];
__device__ __half g_yh [(size_t)ROWS_*INNER_];
__device__ __half g_hh [(size_t)ROWS_*FFH_];

// ---------------- helpers ----------------
__device__ __forceinline__ uint32_t smem_u32(const void* p) {
    uint32_t a;
    asm("{ .reg .u64 t; cvta.to.shared.u64 t, %1; cvt.u32.u64 %0, t; }" : "=r"(a) : "l"(p));
    return a;
}
__device__ __forceinline__ void ldsm_x4(uint32_t (&r)[4], uint32_t a) {
    asm volatile("ldmatrix.sync.aligned.m8n8.x4.shared.b16 {%0,%1,%2,%3}, [%4];"
        : "=r"(r[0]), "=r"(r[1]), "=r"(r[2]), "=r"(r[3]) : "r"(a));
}
__device__ __forceinline__ void mma16816(float (&c)[4], const uint32_t (&a)[4],
                                         uint32_t b0, uint32_t b1) {
    asm volatile("mma.sync.aligned.m16n8k16.row.col.f32.f16.f16.f32 "
        "{%0,%1,%2,%3}, {%4,%5,%6,%7}, {%8,%9}, {%0,%1,%2,%3};"
        : "+f"(c[0]), "+f"(c[1]), "+f"(c[2]), "+f"(c[3])
        : "r"(a[0]), "r"(a[1]), "r"(a[2]), "r"(a[3]), "r"(b0), "r"(b1));
}
__device__ __forceinline__ uint32_t swz(uint32_t row, uint32_t cb, uint32_t pitch) {
    return row * pitch + (((cb) & ~15u) ^ ((row & 7u) * 16u)) + ((cb) & 15u);
}

// ---------------- tile constants ----------------
#define BKC 64
#define TILE_B 16384
#define HTILE_B 8192
#define STAGE2_B (2*TILE_B)
#define STAGE_GG (TILE_B + 2*HTILE_B)
#define GEMM_SMEM  (1024 + 3*STAGE2_B)   // ~97 KB, 2 CTAs/SM
#define GEGLU_SMEM (1024 + 3*STAGE_GG)   // ~97 KB, 2 CTAs/SM
// kv_attn smem aliases:
#define AKT 0
#define AVT 16384
#define AQH 32768
#define AQL 40960
#define AS  49152
#define AP  AQH
#define AMK 81920

// ---------------- fused kv-GEMM + attention ----------------
__global__ __launch_bounds__(256, 2) void kv_attn_kernel(
    const __half* __restrict__ Ah, const __half* __restrict__ Wkt,
    const float* __restrict__ q, const int* __restrict__ mask)
{
    extern __shared__ char smem[];
    const uint32_t tiles = (smem_u32(smem) + 1023u) & ~1023u;
    const int tid = threadIdx.x;
    const int wid = tid >> 5, lid = tid & 31;

    const int bid = blockIdx.x;
    const int sn = bid >> 4;
    const int h  = bid & 15;
    const int s  = sn >> 5;

    const int wm = wid & 1;
    const int wn = wid >> 1;
    const int K = D_;

    const __half* a0 = Ah + (size_t)(sn * B_) * K;
    const __half* bK = Wkt + (size_t)(h * DH_) * K;
    const __half* bV = Wkt + (size_t)(INNER_ + h * DH_) * K;
    const int nch = K / BKC;

    auto load_stage = [&](int st, int kc) {
        const uint32_t sb = tiles + st * STAGE2_B;
        const int kB = kc * BKC * 2;
        #pragma unroll
        for (int j = 0; j < 4; j++) {
            const int i = j * 256 + tid;
            const int r = i >> 3;
            const int c = i & 7;
            const uint32_t d = (uint32_t)(r * 128 + ((c * 16) ^ ((r & 7) * 16)));
            const size_t goA = (size_t)r * K * 2 + kB + c * 16;
            asm volatile("cp.async.cg.shared.global [%0], [%1], 16;"
                :: "r"(sb + d), "l"((const char*)a0 + goA));
            const __half* bsrc = (r < 64) ? (bK + (size_t)r * K)
                                          : (bV + (size_t)(r - 64) * K);
            asm volatile("cp.async.cg.shared.global [%0], [%1], 16;"
                :: "r"(sb + TILE_B + d), "l"((const char*)bsrc + kB + c * 16));
        }
        asm volatile("cp.async.commit_group;" ::: "memory");
    };

    float acc[4][4][4];
    #pragma unroll
    for (int i = 0; i < 4; i++)
        #pragma unroll
        for (int j = 0; j < 4; j++)
            #pragma unroll
            for (int t = 0; t < 4; t++) acc[i][j][t] = 0.f;

    const int lr = lid & 7;
    const int g  = lid >> 3;
    const uint32_t laneXor = (uint32_t)(lr * 16);

    load_stage(0, 0); load_stage(1, 1); load_stage(2, 2);

    for (int kc = 0; kc < nch; kc++) {
        const int st = kc % 3;
        asm volatile("cp.async.wait_group 2;" ::: "memory");
        __syncthreads();
        const uint32_t sb = tiles + st * STAGE2_B;
        #pragma unroll
        for (int kk = 0; kk < 4; kk++) {
            const uint32_t cx = (uint32_t)((kk * 32 + (g >> 1) * 16)) ^ laneXor;
            uint32_t a[4][4];
            #pragma unroll
            for (int i = 0; i < 4; i++) {
                const uint32_t row = (uint32_t)(wm * 64 + i * 16 + lr + (g & 1) * 8);
                ldsm_x4(a[i], sb + row * 128 + cx);
            }
            uint32_t b[2][4];
            #pragma unroll
            for (int jj = 0; jj < 2; jj++) {
                const uint32_t row = (uint32_t)(wn * 32 + jj * 16 + lr + (g & 1) * 8);
                ldsm_x4(b[jj], sb + TILE_B + row * 128 + cx);
            }
            #pragma unroll
            for (int i = 0; i < 4; i++)
                #pragma unroll
                for (int jj = 0; jj < 2; jj++) {
                    mma16816(acc[i][2*jj],   a[i], b[jj][0], b[jj][2]);
                    mma16816(acc[i][2*jj+1], a[i], b[jj][1], b[jj][3]);
                }
        }
        __syncthreads();
        if (kc + 3 < nch) load_stage(st, kc + 3);
    }

    // ---- epilogue: K/V -> smem, load Q hi/lo + mask ----
    const int lr4 = lid >> 2, lc2 = (lid & 3) * 2;
    {
        #pragma unroll
        for (int i = 0; i < 4; i++) {
            #pragma unroll
            for (int j = 0; j < 4; j++) {
                const int mr = wm * 64 + i * 16 + lr4;
                const int cc = wn * 32 + j * 8 + lc2;
                if (cc < 64) {
                    *(__half2*)(smem + AKT + swz((uint32_t)mr, (uint32_t)(cc * 2), 128)) =
                        __halves2half2(__float2half(acc[i][j][0]), __float2half(acc[i][j][1]));
                    *(__half2*)(smem + AKT + swz((uint32_t)(mr + 8), (uint32_t)(cc * 2), 128)) =
                        __halves2half2(__float2half(acc[i][j][2]), __float2half(acc[i][j][3]));
                } else {
                    const int dv = cc - 64;
                    *(__half*)(smem + AVT + swz((uint32_t)dv,     (uint32_t)(mr * 2),       256)) = __float2half(acc[i][j][0]);
                    *(__half*)(smem + AVT + swz((uint32_t)(dv+1), (uint32_t)(mr * 2),       256)) = __float2half(acc[i][j][1]);
                    *(__half*)(smem + AVT + swz((uint32_t)dv,     (uint32_t)((mr + 8) * 2), 256)) = __float2half(acc[i][j][2]);
                    *(__half*)(smem + AVT + swz((uint32_t)(dv+1), (uint32_t)((mr + 8) * 2), 256)) = __float2half(acc[i][j][3]);
                }
            }
        }
        #pragma unroll
        for (int j = 0; j < 4; j++) {
            const int i = j * 256 + tid;
            const int qi = i >> 4, c4 = i & 15;
            const float4 v = *(const float4*)(q + qi * INNER_ + h * DH_ + c4 * 4);
            __half h0 = __float2half(v.x), h1 = __float2half(v.y);
            __half h2 = __float2half(v.z), h3 = __float2half(v.w);
            __half l0 = __float2half(v.x - __half2float(h0));
            __half l1 = __float2half(v.y - __half2float(h1));
            __half l2 = __float2half(v.z - __half2float(h2));
            __half l3 = __float2half(v.w - __half2float(h3));
            const uint32_t off = swz((uint32_t)qi, (uint32_t)(c4 * 8), 128);
            *(__half2*)(smem + AQH + off)     = __halves2half2(h0, h1);
            *(__half2*)(smem + AQH + off + 4) = __halves2half2(h2, h3);
            *(__half2*)(smem + AQL + off)     = __halves2half2(l0, l1);
            *(__half2*)(smem + AQL + off + 4) = __halves2half2(l2, l3);
        }
        if (tid < 128) ((int*)(smem + AMK))[tid] = mask[s * B_ + tid];
    }
    __syncthreads();

    float* sS = (float*)(smem + AS);
    const int* sMask = (const int*)(smem + AMK);
    const uint32_t sbase = tiles;

    // ---- phase 1: sim = Q@K^T (hi/lo) ----
    {
        const int mrow0 = (wid & 3) * 16;
        const int nbase = (wid >> 2) * 64;
        float sacc[8][4];
        #pragma unroll
        for (int f = 0; f < 8; f++)
            #pragma unroll
            for (int t = 0; t < 4; t++) sacc[f][t] = 0.f;
        #pragma unroll
        for (int kk = 0; kk < 4; kk++) {
            const uint32_t cx = (uint32_t)((kk * 32 + (g >> 1) * 16)) ^ laneXor;
            const uint32_t arow = (uint32_t)(mrow0 + lr + (g & 1) * 8);
            uint32_t aH[4], aL[4];
            ldsm_x4(aH, sbase + AQH + arow * 128 + cx);
            ldsm_x4(aL, sbase + AQL + arow * 128 + cx);
            uint32_t b[4][4];
            #pragma unroll
            for (int nn = 0; nn < 4; nn++) {
                const uint32_t brow = (uint32_t)(nbase + nn * 16 + lr + (g & 1) * 8);
                ldsm_x4(b[nn], sbase + AKT + brow * 128 + cx);
            }
            #pragma unroll
            for (int nn = 0; nn < 4; nn++) {
                mma16816(sacc[2*nn],   aH, b[nn][0], b[nn][2]);
                mma16816(sacc[2*nn+1], aH, b[nn][1], b[nn][3]);
            }
            #pragma unroll
            for (int nn = 0; nn < 4; nn++) {
                mma16816(sacc[2*nn],   aL, b[nn][0], b[nn][2]);
                mma16816(sacc[2*nn+1], aL, b[nn][1], b[nn][3]);
            }
        }
        #pragma unroll
        for (int f = 0; f < 8; f++) {
            const int c0 = nbase + f * 8 + lc2;
            const int r0 = mrow0 + lr4;
            const bool m0 = (sMask[c0] == 0), m1 = (sMask[c0 + 1] == 0);
            sS[r0 * B_ + c0]           = m0 ? -1e10f : sacc[f][0] * 0.125f;
            sS[r0 * B_ + c0 + 1]       = m1 ? -1e10f : sacc[f][1] * 0.125f;
            sS[(r0 + 8) * B_ + c0]     = m0 ? -1e10f : sacc[f][2] * 0.125f;
            sS[(r0 + 8) * B_ + c0 + 1] = m1 ? -1e10f : sacc[f][3] * 0.125f;
        }
    }
    __syncthreads();

    // ---- softmax ----
    for (int r = wid * 8; r < wid * 8 + 8; r++) {
        float* row = sS + r * B_;
        float v0 = row[lid], v1 = row[lid + 32], v2 = row[lid + 64], v3 = row[lid + 96];
        float mx = fmaxf(fmaxf(v0, v1), fmaxf(v2, v3));
        #pragma unroll
        for (int o = 16; o > 0; o >>= 1) mx = fmaxf(mx, __shfl_xor_sync(0xffffffffu, mx, o));
        v0 = expf(v0 - mx); v1 = expf(v1 - mx); v2 = expf(v2 - mx); v3 = expf(v3 - mx);
        float sum = v0 + v1 + v2 + v3;
        #pragma unroll
        for (int o = 16; o > 0; o >>= 1) sum += __shfl_xor_sync(0xffffffffu, sum, o);
        const float inv = 1.0f / sum;
        row[lid] = v0 * inv; row[lid + 32] = v1 * inv;
        row[lid + 64] = v2 * inv; row[lid + 96] = v3 * inv;
    }
    __syncthreads();

    // ---- P -> half ----
    #pragma unroll
    for (int j = 0; j < 16; j++) {
        const int i = j * 256 + tid;
        const int r = i >> 6, cp = i & 63;
        const float2 v = *(const float2*)(sS + r * B_ + cp * 2);
        *(__half2*)(smem + AP + swz((uint32_t)r, (uint32_t)(cp * 4), 256)) =
            __halves2half2(__float2half(v.x), __float2half(v.y));
    }
    __syncthreads();

    // ---- phase 3: out = P@V ----
    {
        const int mrow0 = (wid & 3) * 16;
        const int nb = (wid >> 2) * 32;
        float oacc[4][4];
        #pragma unroll
        for (int f = 0; f < 4; f++)
            #pragma unroll
            for (int t = 0; t < 4; t++) oacc[f][t] = 0.f;
        #pragma unroll
        for (int kk = 0; kk < 8; kk++) {
            const uint32_t cx = (uint32_t)((kk * 32 + (g >> 1) * 16)) ^ laneXor;
            const uint32_t arow = (uint32_t)(mrow0 + lr + (g & 1) * 8);
            uint32_t a[4];
            ldsm_x4(a, sbase + AP + arow * 256 + cx);
            uint32_t b[2][4];
            #pragma unroll
            for (int nn = 0; nn < 2; nn++) {
                const uint32_t brow = (uint32_t)(nb + nn * 16 + lr + (g & 1) * 8);
                ldsm_x4(b[nn], sbase + AVT + brow * 256 + cx);
            }
            #pragma unroll
            for (int nn = 0; nn < 2; nn++) {
                mma16816(oacc[2*nn],   a, b[nn][0], b[nn][2]);
                mma16816(oacc[2*nn+1], a, b[nn][1], b[nn][3]);
            }
        }
        __half* outbase = g_atth + (size_t)sn * Q_ * INNER_ + h * DH_;
        #pragma unroll
        for (int f = 0; f < 4; f++) {
            const int dv = nb + f * 8 + lc2;
            const int r0 = mrow0 + lr4;
            *(__half2*)(outbase + (size_t)r0 * INNER_ + dv) =
                __halves2half2(__float2half(oacc[f][0]), __float2half(oacc[f][1]));
            *(__half2*)(outbase + (size_t)(r0 + 8) * INNER_ + dv) =
                __halves2half2(__float2half(oacc[f][2]), __float2half(oacc[f][3]));
        }
    }
}

// ---------------- fp16 GEMM (W2): C = A@B^T + bias + half-residual ----------------
// row_base: starting row (for row-half splits)
__global__ __launch_bounds__(256, 2) void mma_gemm_res(
    const __half* __restrict__ Ah, const __half* __restrict__ Bh,
    float* __restrict__ C, int Nn, int K, int row_base,
    const float* __restrict__ bias, const __half* __restrict__ addh)
{
    extern __shared__ char smem[];
    const uint32_t tiles = (smem_u32(smem) + 1023u) & ~1023u;
    const int tid = threadIdx.x;
    const int wid = tid >> 5, lid = tid & 31;

    const int tiles_n = Nn >> 7;
    const int bid = blockIdx.x;
    const int group = bid / (16 * tiles_n);
    const int rem = bid - group * 16 * tiles_n;
    const int row0 = row_base + (((group << 4) + (rem & 15)) << 7);
    const int col0 = (rem >> 4) << 7;

    const int wm = wid & 1;
    const int wn = wid >> 1;

    const __half* a0 = Ah + (size_t)row0 * K;
    const __half* b0 = Bh + (size_t)col0 * K;
    const int nch = K / BKC;

    auto load_stage = [&](int st, int kc) {
        const uint32_t sb = tiles + st * STAGE2_B;
        const int kB = kc * BKC * 2;
        #pragma unroll
        for (int j = 0; j < 4; j++) {
            const int i = j * 256 + tid;
            const int r = i >> 3;
            const int c = i & 7;
            const uint32_t d = (uint32_t)(r * 128 + ((c * 16) ^ ((r & 7) * 16)));
            const size_t go = (size_t)r * K * 2 + kB + c * 16;
            asm volatile("cp.async.cg.shared.global [%0], [%1], 16;"
                :: "r"(sb + d), "l"((const char*)a0 + go));
            asm volatile("cp.async.cg.shared.global [%0], [%1], 16;"
                :: "r"(sb + TILE_B + d), "l"((const char*)b0 + go));
        }
        asm volatile("cp.async.commit_group;" ::: "memory");
    };

    float acc[4][4][4];
    #pragma unroll
    for (int i = 0; i < 4; i++)
        #pragma unroll
        for (int j = 0; j < 4; j++)
            #pragma unroll
            for (int t = 0; t < 4; t++) acc[i][j][t] = 0.f;

    const int lr = lid & 7;
    const int g  = lid >> 3;
    const uint32_t laneXor = (uint32_t)(lr * 16);

    load_stage(0, 0); load_stage(1, 1); load_stage(2, 2);

    for (int kc = 0; kc < nch; kc++) {
        const int st = kc % 3;
        asm volatile("cp.async.wait_group 2;" ::: "memory");
        __syncthreads();
        const uint32_t sb = tiles + st * STAGE2_B;
        #pragma unroll
        for (int kk = 0; kk < 4; kk++) {
            const uint32_t cx = (uint32_t)((kk * 32 + (g >> 1) * 16)) ^ laneXor;
            uint32_t a[4][4];
            #pragma unroll
            for (int i = 0; i < 4; i++) {
                const uint32_t row = (uint32_t)(wm * 64 + i * 16 + lr + (g & 1) * 8);
                ldsm_x4(a[i], sb + row * 128 + cx);
            }
            uint32_t b[2][4];
            #pragma unroll
            for (int jj = 0; jj < 2; jj++) {
                const uint32_t row = (uint32_t)(wn * 32 + jj * 16 + lr + (g & 1) * 8);
                ldsm_x4(b[jj], sb + TILE_B + row * 128 + cx);
            }
            #pragma unroll
            for (int i = 0; i < 4; i++)
                #pragma unroll
                for (int jj = 0; jj < 2; jj++) {
                    mma16816(acc[i][2*jj],   a[i], b[jj][0], b[jj][2]);
                    mma16816(acc[i][2*jj+1], a[i], b[jj][1], b[jj][3]);
                }
        }
        __syncthreads();
        if (kc + 3 < nch) load_stage(st, kc + 3);
    }

    const int lr4 = lid >> 2, lc2 = (lid & 3) * 2;
    #pragma unroll
    for (int i = 0; i < 4; i++) {
        #pragma unroll
        for (int j = 0; j < 4; j++) {
            const int mr = row0 + wm * 64 + i * 16 + lr4;
            const int cc = col0 + wn * 32 + j * 8 + lc2;
            float2 v0 = make_float2(acc[i][j][0], acc[i][j][1]);
            float2 v1 = make_float2(acc[i][j][2], acc[i][j][3]);
            const float2 bb = *(const float2*)(bias + cc);
            const float2 am0 = __half22float2(*(const __half2*)(addh + (size_t)mr * Nn + cc));
            const float2 am1 = __half22float2(*(const __half2*)(addh + (size_t)(mr + 8) * Nn + cc));
            v0.x += bb.x + am0.x; v0.y += bb.y + am0.y;
            v1.x += bb.x + am1.x; v1.y += bb.y + am1.y;
            *(float2*)(C + (size_t)mr * Nn + cc) = v0;
            *(float2*)(C + (size_t)(mr + 8) * Nn + cc) = v1;
        }
    }
}

// ---------------- fused W1-GEMM + GEGLU: CTA 128x(64a+64g), 2 CTAs/SM ----------------
__global__ __launch_bounds__(256, 2) void mma_gemm_geglu(
    const __half* __restrict__ Ah,
    const __half* __restrict__ Bt,
    const float* __restrict__ bias, int row_base)
{
    extern __shared__ char smem[];
    const uint32_t tiles = (smem_u32(smem) + 1023u) & ~1023u;
    const int tid = threadIdx.x;
    const int wid = tid >> 5, lid = tid & 31;

    const int tiles_n = FFH_ >> 6;
    const int bid = blockIdx.x;
    const int group = bid / (16 * tiles_n);
    const int rem = bid - group * 16 * tiles_n;
    const int row0 = row_base + (((group << 4) + (rem & 15)) << 7);
    const int col0 = (rem >> 4) << 6;

    const int wm = wid & 1;
    const int wn = wid >> 1;
    const int K = INNER_;

    const __half* a0 = Ah + (size_t)row0 * K;
    const __half* ba = Bt + (size_t)col0 * K;
    const __half* bg = Bt + (size_t)(FFH_ + col0) * K;
    const int nch = K / BKC;

    auto load_stage = [&](int st, int kc) {
        const uint32_t sb = tiles + st * STAGE_GG;
        const int kB = kc * BKC * 2;
        #pragma unroll
        for (int j = 0; j < 4; j++) {
            const int i = j * 256 + tid;
            const int r = i >> 3, c = i & 7;
            const uint32_t d = (uint32_t)(r * 128 + ((c * 16) ^ ((r & 7) * 16)));
            const size_t go = (size_t)r * K * 2 + kB + c * 16;
            asm volatile("cp.async.cg.shared.global [%0], [%1], 16;"
                :: "r"(sb + d), "l"((const char*)a0 + go));
        }
        #pragma unroll
        for (int j = 0; j < 2; j++) {
            const int i = j * 256 + tid;
            const int r = i >> 3, c = i & 7;
            const uint32_t d = (uint32_t)(r * 128 + ((c * 16) ^ ((r & 7) * 16)));
            const size_t go = (size_t)r * K * 2 + kB + c * 16;
            asm volatile("cp.async.cg.shared.global [%0], [%1], 16;"
                :: "r"(sb + TILE_B + d), "l"((const char*)ba + go));
            asm volatile("cp.async.cg.shared.global [%0], [%1], 16;"
                :: "r"(sb + TILE_B + HTILE_B + d), "l"((const char*)bg + go));
        }
        asm volatile("cp.async.commit_group;" ::: "memory");
    };

    float acca[4][2][4], accg[4][2][4];
    #pragma unroll
    for (int i = 0; i < 4; i++)
        #pragma unroll
        for (int j = 0; j < 2; j++)
            #pragma unroll
            for (int t = 0; t < 4; t++) { acca[i][j][t] = 0.f; accg[i][j][t] = 0.f; }

    const int lr = lid & 7;
    const int g  = lid >> 3;
    const uint32_t laneXor = (uint32_t)(lr * 16);

    load_stage(0, 0); load_stage(1, 1); load_stage(2, 2);

    for (int kc = 0; kc < nch; kc++) {
        const int st = kc % 3;
        asm volatile("cp.async.wait_group 2;" ::: "memory");
        __syncthreads();
        const uint32_t sb = tiles + st * STAGE_GG;
        #pragma unroll
        for (int kk = 0; kk < 4; kk++) {
            const uint32_t cx = (uint32_t)((kk * 32 + (g >> 1) * 16)) ^ laneXor;
            uint32_t a[4][4];
            #pragma unroll
            for (int i = 0; i < 4; i++) {
                const uint32_t row = (uint32_t)(wm * 64 + i * 16 + lr + (g & 1) * 8);
                ldsm_x4(a[i], sb + row * 128 + cx);
            }
            uint32_t bA[4], bG[4];
            {
                const uint32_t row = (uint32_t)(wn * 16 + lr + (g & 1) * 8);
                ldsm_x4(bA, sb + TILE_B + row * 128 + cx);
                ldsm_x4(bG, sb + TILE_B + HTILE_B + row * 128 + cx);
            }
            #pragma unroll
            for (int i = 0; i < 4; i++) {
                mma16816(acca[i][0], a[i], bA[0], bA[2]);
                mma16816(acca[i][1], a[i], bA[1], bA[3]);
                mma16816(accg[i][0], a[i], bG[0], bG[2]);
                mma16816(accg[i][1], a[i], bG[1], bG[3]);
            }
        }
        __syncthreads();
        if (kc + 3 < nch) load_stage(st, kc + 3);
    }

    const int lr4 = lid >> 2, lc2 = (lid & 3) * 2;
    #pragma unroll
    for (int i = 0; i < 4; i++) {
        #pragma unroll
        for (int j = 0; j < 2; j++) {
            const int mr = row0 + wm * 64 + i * 16 + lr4;
            const int cc = col0 + wn * 16 + j * 8 + lc2;
            const float2 bba = *(const float2*)(bias + cc);
            const float2 bbg = *(const float2*)(bias + FFH_ + cc);
            #pragma unroll
            for (int half_i = 0; half_i < 2; half_i++) {
                const int m = mr + half_i * 8;
                float av0 = acca[i][j][2*half_i]   + bba.x;
                float av1 = acca[i][j][2*half_i+1] + bba.y;
                float gv0 = accg[i][j][2*half_i]   + bbg.x;
                float gv1 = accg[i][j][2*half_i+1] + bbg.y;
                float h0 = av0 * (0.5f * gv0 * (1.0f + erff(gv0 * 0.70710678118654752f)));
                float h1 = av1 * (0.5f * gv1 * (1.0f + erff(gv1 * 0.70710678118654752f)));
                *(__half2*)(g_hh + (size_t)m * FFH_ + cc) =
                    __halves2half2(__float2half(h0), __float2half(h1));
            }
        }
    }
}

// ---------------- prep: x remap -> half (8 elems/thread) ----------------
__global__ __launch_bounds__(256) void prep_x_kernel(const float* __restrict__ x)
{
    const size_t i = (size_t)blockIdx.x * 256 + threadIdx.x;
    const size_t e = i << 3;                       // 8 elements
    const int m = (int)(e >> 10);
    const int col = (int)(e & 1023);
    const int s = m >> 12, rm = m & 4095, n = rm >> 7, b = rm & 127;
    const float* src = x + (((size_t)((s * 128 + b) * 32 + n)) << 10) + col;
    const float4 v0 = *(const float4*)(src);
    const float4 v1 = *(const float4*)(src + 4);
    union { uint4 u; __half2 h[4]; } o;
    o.h[0] = __halves2half2(__float2half(v0.x), __float2half(v0.y));
    o.h[1] = __halves2half2(__float2half(v0.z), __float2half(v0.w));
    o.h[2] = __halves2half2(__float2half(v1.x), __float2half(v1.y));
    o.h[3] = __halves2half2(__float2half(v1.z), __float2half(v1.w));
    *(uint4*)(g_xa + e) = o.u;
}

// ---------------- prep: transpose W -> half ----------------
__global__ __launch_bounds__(256) void tsplit_kernel(
    const float* __restrict__ in, __half* __restrict__ oh, int R, int C)
{
    __shared__ float tile[32][33];
    const int r0 = blockIdx.y * 32, c0 = blockIdx.x * 32;
    const int tx = threadIdx.x, ty = threadIdx.y;
    #pragma unroll
    for (int j = ty; j < 32; j += 8)
        tile[j][tx] = in[(size_t)(r0 + j) * C + c0 + tx];
    __syncthreads();
    #pragma unroll
    for (int j = ty; j < 32; j += 8)
        oh[(size_t)(c0 + j) * R + r0 + tx] = __float2half(tile[tx][j]);
}

// ---------------- LayerNorm: half in, half out ----------------
__global__ __launch_bounds__(256) void ln_kernel(
    const float* __restrict__ gamma, const float* __restrict__ beta)
{
    const int r = blockIdx.x;
    const __half* xr = g_atth + (size_t)r * INNER_;
    const int tid = threadIdx.x;
    const int warp = tid >> 5, lane = tid & 31;

    float v[4];
    float sum = 0.f;
    #pragma unroll
    for (int i = 0; i < 4; i++) { v[i] = __half2float(xr[tid + i * 256]); sum += v[i]; }

    __shared__ float red[8];
    #pragma unroll
    for (int o = 16; o > 0; o >>= 1) sum += __shfl_xor_sync(0xffffffffu, sum, o);
    if (lane == 0) red[warp] = sum;
    __syncthreads();
    float tot = red[lane & 7];
    #pragma unroll
    for (int o = 4; o > 0; o >>= 1) tot += __shfl_xor_sync(0xffffffffu, tot, o);
    float mean = tot * (1.0f / 1024.0f);

    float sq = 0.f;
    #pragma unroll
    for (int i = 0; i < 4; i++) { float d = v[i] - mean; sq += d * d; }
    #pragma unroll
    for (int o = 16; o > 0; o >>= 1) sq += __shfl_xor_sync(0xffffffffu, sq, o);
    __syncthreads();
    if (lane == 0) red[warp] = sq;
    __syncthreads();
    float tot2 = red[lane & 7];
    #pragma unroll
    for (int o = 4; o > 0; o >>= 1) tot2 += __shfl_xor_sync(0xffffffffu, tot2, o);
    float var = tot2 * (1.0f / 1024.0f);
    float inv = rsqrtf(var + 1e-5f);

    #pragma unroll
    for (int i = 0; i < 4; i++) {
        int c = tid + i * 256;
        float yv = (v[i] - mean) * inv * gamma[c] + beta[c];
        g_yh[(size_t)r * INNER_ + c] = __float2half(yv);
    }
}

// ---------------- stream pack (static init; no device allocs) ----------------
struct StreamPack {
    cudaStream_t s1 = nullptr;
    cudaEvent_t eF = nullptr, eK = nullptr, e1 = nullptr, e2 = nullptr;
    cudaEvent_t eg0 = nullptr, ew0 = nullptr;
    bool ok = false;
    StreamPack() {
        ok = (cudaStreamCreateWithFlags(&s1, cudaStreamNonBlocking) == cudaSuccess) &&
             (cudaEventCreateWithFlags(&eF,  cudaEventDisableTiming) == cudaSuccess) &&
             (cudaEventCreateWithFlags(&eK,  cudaEventDisableTiming) == cudaSuccess) &&
             (cudaEventCreateWithFlags(&e1,  cudaEventDisableTiming) == cudaSuccess) &&
             (cudaEventCreateWithFlags(&e2,  cudaEventDisableTiming) == cudaSuccess) &&
             (cudaEventCreateWithFlags(&eg0, cudaEventDisableTiming) == cudaSuccess) &&
             (cudaEventCreateWithFlags(&ew0, cudaEventDisableTiming) == cudaSuccess);
    }
};
static StreamPack g_sp;

// ---------------- launch ----------------
extern "C" void kernel_launch(void* const* d_in, const int* in_sizes, int n_in,
                              void* d_out, int out_size)
{
    const float* x    = (const float*)d_in[0];
    const int*   mask = (const int*)  d_in[1];
    const float* q    = (const float*)d_in[2];
    const float* W_kv = (const float*)d_in[3];
    const float* ln_g = (const float*)d_in[4];
    const float* ln_b = (const float*)d_in[5];
    const float* W1   = (const float*)d_in[6];
    const float* b1   = (const float*)d_in[7];
    const float* W2   = (const float*)d_in[8];
    const float* b2   = (const float*)d_in[9];
    float* out = (float*)d_out;
    (void)in_sizes; (void)n_in; (void)out_size;

    __half *xa, *wkt, *w1t, *w2t, *yh, *hh;
    cudaGetSymbolAddress((void**)&xa,  g_xa);
    cudaGetSymbolAddress((void**)&wkt, g_wkt);
    cudaGetSymbolAddress((void**)&w1t, g_w1t);
    cudaGetSymbolAddress((void**)&w2t, g_w2t);
    cudaGetSymbolAddress((void**)&yh,  g_yh);
    cudaGetSymbolAddress((void**)&hh,  g_hh);

    cudaFuncSetAttribute(kv_attn_kernel, cudaFuncAttributeMaxDynamicSharedMemorySize, GEMM_SMEM);
    cudaFuncSetAttribute(mma_gemm_res,   cudaFuncAttributeMaxDynamicSharedMemorySize, GEMM_SMEM);
    cudaFuncSetAttribute(mma_gemm_geglu, cudaFuncAttributeMaxDynamicSharedMemorySize, GEGLU_SMEM);

    const int HROWS = ROWS_ / 2;   // 8192
    const int GG_HGRID = (HROWS / 128) * (FFH_ / 64);     // 4096
    const int W2_HGRID = (HROWS / 128) * (INNER_ / 128);  // 512

    dim3 tb(32, 8);
    if (g_sp.ok) {
        cudaEventRecord(g_sp.eF, 0);
        cudaStreamWaitEvent(g_sp.s1, g_sp.eF, 0);
        tsplit_kernel<<<dim3(KVW_ / 32, D_ / 32), tb, 0, g_sp.s1>>>(W_kv, wkt, D_, KVW_);
        cudaEventRecord(g_sp.eK, g_sp.s1);
        tsplit_kernel<<<dim3(FF2_ / 32, INNER_ / 32), tb, 0, g_sp.s1>>>(W1, w1t, INNER_, FF2_);
        cudaEventRecord(g_sp.e1, g_sp.s1);
        tsplit_kernel<<<dim3(INNER_ / 32, FFH_ / 32), tb, 0, g_sp.s1>>>(W2, w2t, FFH_, INNER_);
        cudaEventRecord(g_sp.e2, g_sp.s1);

        prep_x_kernel<<<(KVROWS_ * (size_t)D_) / 8 / 256, 256>>>(x);
        cudaStreamWaitEvent(0, g_sp.eK, 0);
        kv_attn_kernel<<<256 * HEADS_, 256, GEMM_SMEM>>>(xa, wkt, q, mask);
        ln_kernel<<<ROWS_, 256>>>(ln_g, ln_b);
        cudaStreamWaitEvent(0, g_sp.e1, 0);
        // geglu half 0 on main
        mma_gemm_geglu<<<GG_HGRID, 256, GEGLU_SMEM>>>(yh, w1t, b1, 0);
        cudaEventRecord(g_sp.eg0, 0);
        // geglu half 1 on main; W2 half 0 on s1 (overlaps gg1)
        cudaStreamWaitEvent(g_sp.s1, g_sp.eg0, 0);
        mma_gemm_res<<<W2_HGRID, 256, GEMM_SMEM, g_sp.s1>>>(
            hh, w2t, out, INNER_, FFH_, 0, b2, yh);
        cudaEventRecord(g_sp.ew0, g_sp.s1);
        mma_gemm_geglu<<<GG_HGRID, 256, GEGLU_SMEM>>>(yh, w1t, b1, HROWS);
        cudaStreamWaitEvent(0, g_sp.e2, 0);
        // W2 half 1 on main
        mma_gemm_res<<<W2_HGRID, 256, GEMM_SMEM>>>(
            hh, w2t, out, INNER_, FFH_, HROWS, b2, yh);
        // join s1 back into main
        cudaStreamWaitEvent(0, g_sp.ew0, 0);
    } else {
        prep_x_kernel<<<(KVROWS_ * (size_t)D_) / 8 / 256, 256>>>(x);
        tsplit_kernel<<<dim3(KVW_ / 32, D_ / 32), tb>>>(W_kv, wkt, D_, KVW_);
        tsplit_kernel<<<dim3(FF2_ / 32, INNER_ / 32), tb>>>(W1, w1t, INNER_, FF2_);
        tsplit_kernel<<<dim3(INNER_ / 32, FFH_ / 32), tb>>>(W2, w2t, FFH_, INNER_);
        kv_attn_kernel<<<256 * HEADS_, 256, GEMM_SMEM>>>(xa, wkt, q, mask);
        ln_kernel<<<ROWS_, 256>>>(ln_g, ln_b);
        mma_gemm_geglu<<<(ROWS_ / 128) * (FFH_ / 64), 256, GEGLU_SMEM>>>(yh, w1t, b1, 0);
        mma_gemm_res<<<(ROWS_ / 128) * (INNER_ / 128), 256, GEMM_SMEM>>>(
            hh, w2t, out, INNER_, FFH_, 0, b2, yh);
    }
}

// round 15
// speedup vs baseline: 1.0064x; 1.0064x over previous
#include <cuda_runtime.h>
#include <cuda_fp16.h>
#include <math.h>
#include <stdint.h>

// ---------------- problem constants ----------------
#define S_     8
#define B_     128
#define N_     32
#define D_     1024
#define HEADS_ 16
#define DH_    64
#define Q_     64
#define INNER_ 1024
#define KVW_   2048
#define FFH_   4096
#define FF2_   8192
#define ROWS_  (S_*N_*Q_)    // 16384
#define KVROWS_ (S_*N_*B_)   // 32768

// ---------------- scratch ----------------
__device__ __half g_atth[(size_t)ROWS_*INNER_];
__device__ __half g_xa [(size_t)KVROWS_*D_];
__device__ __half g_wkt[(size_t)KVW_*D_];
__device__ __half g_w1t[(size_t)FF2_*INNER_];
__device__ __half g_w2t[(size_t)INNER_*FFH_];
__device__ __half g_yh [(size_t)ROWS_*INNER_];
__device__ __half g_hh [(size_t)ROWS_*FFH_];

// ---------------- helpers ----------------
__device__ __forceinline__ uint32_t smem_u32(const void* p) {
    uint32_t a;
    asm("{ .reg .u64 t; cvta.to.shared.u64 t, %1; cvt.u32.u64 %0, t; }" : "=r"(a) : "l"(p));
    return a;
}
__device__ __forceinline__ void ldsm_x4(uint32_t (&r)[4], uint32_t a) {
    asm volatile("ldmatrix.sync.aligned.m8n8.x4.shared.b16 {%0,%1,%2,%3}, [%4];"
        : "=r"(r[0]), "=r"(r[1]), "=r"(r[2]), "=r"(r[3]) : "r"(a));
}
__device__ __forceinline__ void mma16816(float (&c)[4], const uint32_t (&a)[4],
                                         uint32_t b0, uint32_t b1) {
    asm volatile("mma.sync.aligned.m16n8k16.row.col.f32.f16.f16.f32 "
        "{%0,%1,%2,%3}, {%4,%5,%6,%7}, {%8,%9}, {%0,%1,%2,%3};"
        : "+f"(c[0]), "+f"(c[1]), "+f"(c[2]), "+f"(c[3])
        : "r"(a[0]), "r"(a[1]), "r"(a[2]), "r"(a[3]), "r"(b0), "r"(b1));
}
__device__ __forceinline__ uint32_t swz(uint32_t row, uint32_t cb, uint32_t pitch) {
    return row * pitch + (((cb) & ~15u) ^ ((row & 7u) * 16u)) + ((cb) & 15u);
}

// ---------------- tile constants ----------------
#define BKC 64
#define TILE_B 16384
#define HTILE_B 8192
#define STAGE2_B (2*TILE_B)
#define STAGE_GG (TILE_B + 2*HTILE_B)
#define GEMM_SMEM  (1024 + 3*STAGE2_B)   // ~97 KB, 2 CTAs/SM
#define GEGLU_SMEM (1024 + 3*STAGE_GG)   // ~97 KB, 2 CTAs/SM
// kv_attn smem aliases:
#define AKT 0
#define AVT 16384
#define AQH 32768
#define AQL 40960
#define AS  49152
#define AP  AQH
#define AMK 81920

// ---------------- fused kv-GEMM + attention ----------------
__global__ __launch_bounds__(256, 2) void kv_attn_kernel(
    const __half* __restrict__ Ah, const __half* __restrict__ Wkt,
    const float* __restrict__ q, const int* __restrict__ mask)
{
    extern __shared__ char smem[];
    const uint32_t tiles = (smem_u32(smem) + 1023u) & ~1023u;
    const int tid = threadIdx.x;
    const int wid = tid >> 5, lid = tid & 31;

    const int bid = blockIdx.x;
    const int sn = bid >> 4;
    const int h  = bid & 15;
    const int s  = sn >> 5;

    const int wm = wid & 1;
    const int wn = wid >> 1;
    const int K = D_;

    const __half* a0 = Ah + (size_t)(sn * B_) * K;
    const __half* bK = Wkt + (size_t)(h * DH_) * K;
    const __half* bV = Wkt + (size_t)(INNER_ + h * DH_) * K;
    const int nch = K / BKC;

    auto load_stage = [&](int st, int kc) {
        const uint32_t sb = tiles + st * STAGE2_B;
        const int kB = kc * BKC * 2;
        #pragma unroll
        for (int j = 0; j < 4; j++) {
            const int i = j * 256 + tid;
            const int r = i >> 3;
            const int c = i & 7;
            const uint32_t d = (uint32_t)(r * 128 + ((c * 16) ^ ((r & 7) * 16)));
            const size_t goA = (size_t)r * K * 2 + kB + c * 16;
            asm volatile("cp.async.cg.shared.global [%0], [%1], 16;"
                :: "r"(sb + d), "l"((const char*)a0 + goA));
            const __half* bsrc = (r < 64) ? (bK + (size_t)r * K)
                                          : (bV + (size_t)(r - 64) * K);
            asm volatile("cp.async.cg.shared.global [%0], [%1], 16;"
                :: "r"(sb + TILE_B + d), "l"((const char*)bsrc + kB + c * 16));
        }
        asm volatile("cp.async.commit_group;" ::: "memory");
    };

    float acc[4][4][4];
    #pragma unroll
    for (int i = 0; i < 4; i++)
        #pragma unroll
        for (int j = 0; j < 4; j++)
            #pragma unroll
            for (int t = 0; t < 4; t++) acc[i][j][t] = 0.f;

    const int lr = lid & 7;
    const int g  = lid >> 3;
    const uint32_t laneXor = (uint32_t)(lr * 16);

    load_stage(0, 0); load_stage(1, 1); load_stage(2, 2);

    for (int kc = 0; kc < nch; kc++) {
        const int st = kc % 3;
        asm volatile("cp.async.wait_group 2;" ::: "memory");
        __syncthreads();
        const uint32_t sb = tiles + st * STAGE2_B;
        #pragma unroll
        for (int kk = 0; kk < 4; kk++) {
            const uint32_t cx = (uint32_t)((kk * 32 + (g >> 1) * 16)) ^ laneXor;
            uint32_t a[4][4];
            #pragma unroll
            for (int i = 0; i < 4; i++) {
                const uint32_t row = (uint32_t)(wm * 64 + i * 16 + lr + (g & 1) * 8);
                ldsm_x4(a[i], sb + row * 128 + cx);
            }
            uint32_t b[2][4];
            #pragma unroll
            for (int jj = 0; jj < 2; jj++) {
                const uint32_t row = (uint32_t)(wn * 32 + jj * 16 + lr + (g & 1) * 8);
                ldsm_x4(b[jj], sb + TILE_B + row * 128 + cx);
            }
            #pragma unroll
            for (int i = 0; i < 4; i++)
                #pragma unroll
                for (int jj = 0; jj < 2; jj++) {
                    mma16816(acc[i][2*jj],   a[i], b[jj][0], b[jj][2]);
                    mma16816(acc[i][2*jj+1], a[i], b[jj][1], b[jj][3]);
                }
        }
        __syncthreads();
        if (kc + 3 < nch) load_stage(st, kc + 3);
    }

    // ---- epilogue: K/V -> smem, load Q hi/lo + mask ----
    const int lr4 = lid >> 2, lc2 = (lid & 3) * 2;
    {
        #pragma unroll
        for (int i = 0; i < 4; i++) {
            #pragma unroll
            for (int j = 0; j < 4; j++) {
                const int mr = wm * 64 + i * 16 + lr4;
                const int cc = wn * 32 + j * 8 + lc2;
                if (cc < 64) {
                    *(__half2*)(smem + AKT + swz((uint32_t)mr, (uint32_t)(cc * 2), 128)) =
                        __halves2half2(__float2half(acc[i][j][0]), __float2half(acc[i][j][1]));
                    *(__half2*)(smem + AKT + swz((uint32_t)(mr + 8), (uint32_t)(cc * 2), 128)) =
                        __halves2half2(__float2half(acc[i][j][2]), __float2half(acc[i][j][3]));
                } else {
                    const int dv = cc - 64;
                    *(__half*)(smem + AVT + swz((uint32_t)dv,     (uint32_t)(mr * 2),       256)) = __float2half(acc[i][j][0]);
                    *(__half*)(smem + AVT + swz((uint32_t)(dv+1), (uint32_t)(mr * 2),       256)) = __float2half(acc[i][j][1]);
                    *(__half*)(smem + AVT + swz((uint32_t)dv,     (uint32_t)((mr + 8) * 2), 256)) = __float2half(acc[i][j][2]);
                    *(__half*)(smem + AVT + swz((uint32_t)(dv+1), (uint32_t)((mr + 8) * 2), 256)) = __float2half(acc[i][j][3]);
                }
            }
        }
        #pragma unroll
        for (int j = 0; j < 4; j++) {
            const int i = j * 256 + tid;
            const int qi = i >> 4, c4 = i & 15;
            const float4 v = *(const float4*)(q + qi * INNER_ + h * DH_ + c4 * 4);
            __half h0 = __float2half(v.x), h1 = __float2half(v.y);
            __half h2 = __float2half(v.z), h3 = __float2half(v.w);
            __half l0 = __float2half(v.x - __half2float(h0));
            __half l1 = __float2half(v.y - __half2float(h1));
            __half l2 = __float2half(v.z - __half2float(h2));
            __half l3 = __float2half(v.w - __half2float(h3));
            const uint32_t off = swz((uint32_t)qi, (uint32_t)(c4 * 8), 128);
            *(__half2*)(smem + AQH + off)     = __halves2half2(h0, h1);
            *(__half2*)(smem + AQH + off + 4) = __halves2half2(h2, h3);
            *(__half2*)(smem + AQL + off)     = __halves2half2(l0, l1);
            *(__half2*)(smem + AQL + off + 4) = __halves2half2(l2, l3);
        }
        if (tid < 128) ((int*)(smem + AMK))[tid] = mask[s * B_ + tid];
    }
    __syncthreads();

    float* sS = (float*)(smem + AS);
    const int* sMask = (const int*)(smem + AMK);
    const uint32_t sbase = tiles;

    // ---- phase 1: sim = Q@K^T (hi/lo) ----
    {
        const int mrow0 = (wid & 3) * 16;
        const int nbase = (wid >> 2) * 64;
        float sacc[8][4];
        #pragma unroll
        for (int f = 0; f < 8; f++)
            #pragma unroll
            for (int t = 0; t < 4; t++) sacc[f][t] = 0.f;
        #pragma unroll
        for (int kk = 0; kk < 4; kk++) {
            const uint32_t cx = (uint32_t)((kk * 32 + (g >> 1) * 16)) ^ laneXor;
            const uint32_t arow = (uint32_t)(mrow0 + lr + (g & 1) * 8);
            uint32_t aH[4], aL[4];
            ldsm_x4(aH, sbase + AQH + arow * 128 + cx);
            ldsm_x4(aL, sbase + AQL + arow * 128 + cx);
            uint32_t b[4][4];
            #pragma unroll
            for (int nn = 0; nn < 4; nn++) {
                const uint32_t brow = (uint32_t)(nbase + nn * 16 + lr + (g & 1) * 8);
                ldsm_x4(b[nn], sbase + AKT + brow * 128 + cx);
            }
            #pragma unroll
            for (int nn = 0; nn < 4; nn++) {
                mma16816(sacc[2*nn],   aH, b[nn][0], b[nn][2]);
                mma16816(sacc[2*nn+1], aH, b[nn][1], b[nn][3]);
            }
            #pragma unroll
            for (int nn = 0; nn < 4; nn++) {
                mma16816(sacc[2*nn],   aL, b[nn][0], b[nn][2]);
                mma16816(sacc[2*nn+1], aL, b[nn][1], b[nn][3]);
            }
        }
        #pragma unroll
        for (int f = 0; f < 8; f++) {
            const int c0 = nbase + f * 8 + lc2;
            const int r0 = mrow0 + lr4;
            const bool m0 = (sMask[c0] == 0), m1 = (sMask[c0 + 1] == 0);
            sS[r0 * B_ + c0]           = m0 ? -1e10f : sacc[f][0] * 0.125f;
            sS[r0 * B_ + c0 + 1]       = m1 ? -1e10f : sacc[f][1] * 0.125f;
            sS[(r0 + 8) * B_ + c0]     = m0 ? -1e10f : sacc[f][2] * 0.125f;
            sS[(r0 + 8) * B_ + c0 + 1] = m1 ? -1e10f : sacc[f][3] * 0.125f;
        }
    }
    __syncthreads();

    // ---- softmax ----
    for (int r = wid * 8; r < wid * 8 + 8; r++) {
        float* row = sS + r * B_;
        float v0 = row[lid], v1 = row[lid + 32], v2 = row[lid + 64], v3 = row[lid + 96];
        float mx = fmaxf(fmaxf(v0, v1), fmaxf(v2, v3));
        #pragma unroll
        for (int o = 16; o > 0; o >>= 1) mx = fmaxf(mx, __shfl_xor_sync(0xffffffffu, mx, o));
        v0 = expf(v0 - mx); v1 = expf(v1 - mx); v2 = expf(v2 - mx); v3 = expf(v3 - mx);
        float sum = v0 + v1 + v2 + v3;
        #pragma unroll
        for (int o = 16; o > 0; o >>= 1) sum += __shfl_xor_sync(0xffffffffu, sum, o);
        const float inv = 1.0f / sum;
        row[lid] = v0 * inv; row[lid + 32] = v1 * inv;
        row[lid + 64] = v2 * inv; row[lid + 96] = v3 * inv;
    }
    __syncthreads();

    // ---- P -> half ----
    #pragma unroll
    for (int j = 0; j < 16; j++) {
        const int i = j * 256 + tid;
        const int r = i >> 6, cp = i & 63;
        const float2 v = *(const float2*)(sS + r * B_ + cp * 2);
        *(__half2*)(smem + AP + swz((uint32_t)r, (uint32_t)(cp * 4), 256)) =
            __halves2half2(__float2half(v.x), __float2half(v.y));
    }
    __syncthreads();

    // ---- phase 3: out = P@V ----
    {
        const int mrow0 = (wid & 3) * 16;
        const int nb = (wid >> 2) * 32;
        float oacc[4][4];
        #pragma unroll
        for (int f = 0; f < 4; f++)
            #pragma unroll
            for (int t = 0; t < 4; t++) oacc[f][t] = 0.f;
        #pragma unroll
        for (int kk = 0; kk < 8; kk++) {
            const uint32_t cx = (uint32_t)((kk * 32 + (g >> 1) * 16)) ^ laneXor;
            const uint32_t arow = (uint32_t)(mrow0 + lr + (g & 1) * 8);
            uint32_t a[4];
            ldsm_x4(a, sbase + AP + arow * 256 + cx);
            uint32_t b[2][4];
            #pragma unroll
            for (int nn = 0; nn < 2; nn++) {
                const uint32_t brow = (uint32_t)(nb + nn * 16 + lr + (g & 1) * 8);
                ldsm_x4(b[nn], sbase + AVT + brow * 256 + cx);
            }
            #pragma unroll
            for (int nn = 0; nn < 2; nn++) {
                mma16816(oacc[2*nn],   a, b[nn][0], b[nn][2]);
                mma16816(oacc[2*nn+1], a, b[nn][1], b[nn][3]);
            }
        }
        __half* outbase = g_atth + (size_t)sn * Q_ * INNER_ + h * DH_;
        #pragma unroll
        for (int f = 0; f < 4; f++) {
            const int dv = nb + f * 8 + lc2;
            const int r0 = mrow0 + lr4;
            *(__half2*)(outbase + (size_t)r0 * INNER_ + dv) =
                __halves2half2(__float2half(oacc[f][0]), __float2half(oacc[f][1]));
            *(__half2*)(outbase + (size_t)(r0 + 8) * INNER_ + dv) =
                __halves2half2(__float2half(oacc[f][2]), __float2half(oacc[f][3]));
        }
    }
}

// ---------------- fp16 GEMM (W2): C = A@B^T + bias + half-residual ----------------
__global__ __launch_bounds__(256, 2) void mma_gemm_res(
    const __half* __restrict__ Ah, const __half* __restrict__ Bh,
    float* __restrict__ C, int Nn, int K,
    const float* __restrict__ bias, const __half* __restrict__ addh)
{
    extern __shared__ char smem[];
    const uint32_t tiles = (smem_u32(smem) + 1023u) & ~1023u;
    const int tid = threadIdx.x;
    const int wid = tid >> 5, lid = tid & 31;

    const int tiles_n = Nn >> 7;
    const int bid = blockIdx.x;
    const int group = bid / (16 * tiles_n);
    const int rem = bid - group * 16 * tiles_n;
    const int row0 = ((group << 4) + (rem & 15)) << 7;
    const int col0 = (rem >> 4) << 7;

    const int wm = wid & 1;
    const int wn = wid >> 1;

    const __half* a0 = Ah + (size_t)row0 * K;
    const __half* b0 = Bh + (size_t)col0 * K;
    const int nch = K / BKC;

    auto load_stage = [&](int st, int kc) {
        const uint32_t sb = tiles + st * STAGE2_B;
        const int kB = kc * BKC * 2;
        #pragma unroll
        for (int j = 0; j < 4; j++) {
            const int i = j * 256 + tid;
            const int r = i >> 3;
            const int c = i & 7;
            const uint32_t d = (uint32_t)(r * 128 + ((c * 16) ^ ((r & 7) * 16)));
            const size_t go = (size_t)r * K * 2 + kB + c * 16;
            asm volatile("cp.async.cg.shared.global [%0], [%1], 16;"
                :: "r"(sb + d), "l"((const char*)a0 + go));
            asm volatile("cp.async.cg.shared.global [%0], [%1], 16;"
                :: "r"(sb + TILE_B + d), "l"((const char*)b0 + go));
        }
        asm volatile("cp.async.commit_group;" ::: "memory");
    };

    float acc[4][4][4];
    #pragma unroll
    for (int i = 0; i < 4; i++)
        #pragma unroll
        for (int j = 0; j < 4; j++)
            #pragma unroll
            for (int t = 0; t < 4; t++) acc[i][j][t] = 0.f;

    const int lr = lid & 7;
    const int g  = lid >> 3;
    const uint32_t laneXor = (uint32_t)(lr * 16);

    load_stage(0, 0); load_stage(1, 1); load_stage(2, 2);

    for (int kc = 0; kc < nch; kc++) {
        const int st = kc % 3;
        asm volatile("cp.async.wait_group 2;" ::: "memory");
        __syncthreads();
        const uint32_t sb = tiles + st * STAGE2_B;
        #pragma unroll
        for (int kk = 0; kk < 4; kk++) {
            const uint32_t cx = (uint32_t)((kk * 32 + (g >> 1) * 16)) ^ laneXor;
            uint32_t a[4][4];
            #pragma unroll
            for (int i = 0; i < 4; i++) {
                const uint32_t row = (uint32_t)(wm * 64 + i * 16 + lr + (g & 1) * 8);
                ldsm_x4(a[i], sb + row * 128 + cx);
            }
            uint32_t b[2][4];
            #pragma unroll
            for (int jj = 0; jj < 2; jj++) {
                const uint32_t row = (uint32_t)(wn * 32 + jj * 16 + lr + (g & 1) * 8);
                ldsm_x4(b[jj], sb + TILE_B + row * 128 + cx);
            }
            #pragma unroll
            for (int i = 0; i < 4; i++)
                #pragma unroll
                for (int jj = 0; jj < 2; jj++) {
                    mma16816(acc[i][2*jj],   a[i], b[jj][0], b[jj][2]);
                    mma16816(acc[i][2*jj+1], a[i], b[jj][1], b[jj][3]);
                }
        }
        __syncthreads();
        if (kc + 3 < nch) load_stage(st, kc + 3);
    }

    const int lr4 = lid >> 2, lc2 = (lid & 3) * 2;
    #pragma unroll
    for (int i = 0; i < 4; i++) {
        #pragma unroll
        for (int j = 0; j < 4; j++) {
            const int mr = row0 + wm * 64 + i * 16 + lr4;
            const int cc = col0 + wn * 32 + j * 8 + lc2;
            float2 v0 = make_float2(acc[i][j][0], acc[i][j][1]);
            float2 v1 = make_float2(acc[i][j][2], acc[i][j][3]);
            const float2 bb = *(const float2*)(bias + cc);
            const float2 am0 = __half22float2(*(const __half2*)(addh + (size_t)mr * Nn + cc));
            const float2 am1 = __half22float2(*(const __half2*)(addh + (size_t)(mr + 8) * Nn + cc));
            v0.x += bb.x + am0.x; v0.y += bb.y + am0.y;
            v1.x += bb.x + am1.x; v1.y += bb.y + am1.y;
            *(float2*)(C + (size_t)mr * Nn + cc) = v0;
            *(float2*)(C + (size_t)(mr + 8) * Nn + cc) = v1;
        }
    }
}

// ---------------- fused W1-GEMM + GEGLU: CTA 128x(64a+64g), 2 CTAs/SM ----------------
__global__ __launch_bounds__(256, 2) void mma_gemm_geglu(
    const __half* __restrict__ Ah,
    const __half* __restrict__ Bt,
    const float* __restrict__ bias)
{
    extern __shared__ char smem[];
    const uint32_t tiles = (smem_u32(smem) + 1023u) & ~1023u;
    const int tid = threadIdx.x;
    const int wid = tid >> 5, lid = tid & 31;

    const int tiles_n = FFH_ >> 6;
    const int bid = blockIdx.x;
    const int group = bid / (16 * tiles_n);
    const int rem = bid - group * 16 * tiles_n;
    const int row0 = ((group << 4) + (rem & 15)) << 7;
    const int col0 = (rem >> 4) << 6;

    const int wm = wid & 1;
    const int wn = wid >> 1;
    const int K = INNER_;

    const __half* a0 = Ah + (size_t)row0 * K;
    const __half* ba = Bt + (size_t)col0 * K;
    const __half* bg = Bt + (size_t)(FFH_ + col0) * K;
    const int nch = K / BKC;

    auto load_stage = [&](int st, int kc) {
        const uint32_t sb = tiles + st * STAGE_GG;
        const int kB = kc * BKC * 2;
        #pragma unroll
        for (int j = 0; j < 4; j++) {
            const int i = j * 256 + tid;
            const int r = i >> 3, c = i & 7;
            const uint32_t d = (uint32_t)(r * 128 + ((c * 16) ^ ((r & 7) * 16)));
            const size_t go = (size_t)r * K * 2 + kB + c * 16;
            asm volatile("cp.async.cg.shared.global [%0], [%1], 16;"
                :: "r"(sb + d), "l"((const char*)a0 + go));
        }
        #pragma unroll
        for (int j = 0; j < 2; j++) {
            const int i = j * 256 + tid;
            const int r = i >> 3, c = i & 7;
            const uint32_t d = (uint32_t)(r * 128 + ((c * 16) ^ ((r & 7) * 16)));
            const size_t go = (size_t)r * K * 2 + kB + c * 16;
            asm volatile("cp.async.cg.shared.global [%0], [%1], 16;"
                :: "r"(sb + TILE_B + d), "l"((const char*)ba + go));
            asm volatile("cp.async.cg.shared.global [%0], [%1], 16;"
                :: "r"(sb + TILE_B + HTILE_B + d), "l"((const char*)bg + go));
        }
        asm volatile("cp.async.commit_group;" ::: "memory");
    };

    float acca[4][2][4], accg[4][2][4];
    #pragma unroll
    for (int i = 0; i < 4; i++)
        #pragma unroll
        for (int j = 0; j < 2; j++)
            #pragma unroll
            for (int t = 0; t < 4; t++) { acca[i][j][t] = 0.f; accg[i][j][t] = 0.f; }

    const int lr = lid & 7;
    const int g  = lid >> 3;
    const uint32_t laneXor = (uint32_t)(lr * 16);

    load_stage(0, 0); load_stage(1, 1); load_stage(2, 2);

    for (int kc = 0; kc < nch; kc++) {
        const int st = kc % 3;
        asm volatile("cp.async.wait_group 2;" ::: "memory");
        __syncthreads();
        const uint32_t sb = tiles + st * STAGE_GG;
        #pragma unroll
        for (int kk = 0; kk < 4; kk++) {
            const uint32_t cx = (uint32_t)((kk * 32 + (g >> 1) * 16)) ^ laneXor;
            uint32_t a[4][4];
            #pragma unroll
            for (int i = 0; i < 4; i++) {
                const uint32_t row = (uint32_t)(wm * 64 + i * 16 + lr + (g & 1) * 8);
                ldsm_x4(a[i], sb + row * 128 + cx);
            }
            uint32_t bA[4], bG[4];
            {
                const uint32_t row = (uint32_t)(wn * 16 + lr + (g & 1) * 8);
                ldsm_x4(bA, sb + TILE_B + row * 128 + cx);
                ldsm_x4(bG, sb + TILE_B + HTILE_B + row * 128 + cx);
            }
            #pragma unroll
            for (int i = 0; i < 4; i++) {
                mma16816(acca[i][0], a[i], bA[0], bA[2]);
                mma16816(acca[i][1], a[i], bA[1], bA[3]);
                mma16816(accg[i][0], a[i], bG[0], bG[2]);
                mma16816(accg[i][1], a[i], bG[1], bG[3]);
            }
        }
        __syncthreads();
        if (kc + 3 < nch) load_stage(st, kc + 3);
    }

    const int lr4 = lid >> 2, lc2 = (lid & 3) * 2;
    #pragma unroll
    for (int i = 0; i < 4; i++) {
        #pragma unroll
        for (int j = 0; j < 2; j++) {
            const int mr = row0 + wm * 64 + i * 16 + lr4;
            const int cc = col0 + wn * 16 + j * 8 + lc2;
            const float2 bba = *(const float2*)(bias + cc);
            const float2 bbg = *(const float2*)(bias + FFH_ + cc);
            #pragma unroll
            for (int half_i = 0; half_i < 2; half_i++) {
                const int m = mr + half_i * 8;
                float av0 = acca[i][j][2*half_i]   + bba.x;
                float av1 = acca[i][j][2*half_i+1] + bba.y;
                float gv0 = accg[i][j][2*half_i]   + bbg.x;
                float gv1 = accg[i][j][2*half_i+1] + bbg.y;
                float h0 = av0 * (0.5f * gv0 * (1.0f + erff(gv0 * 0.70710678118654752f)));
                float h1 = av1 * (0.5f * gv1 * (1.0f + erff(gv1 * 0.70710678118654752f)));
                *(__half2*)(g_hh + (size_t)m * FFH_ + cc) =
                    __halves2half2(__float2half(h0), __float2half(h1));
            }
        }
    }
}

// ---------------- prep: x remap -> half (8 elems/thread) ----------------
__global__ __launch_bounds__(256) void prep_x_kernel(const float* __restrict__ x)
{
    const size_t i = (size_t)blockIdx.x * 256 + threadIdx.x;
    const size_t e = i << 3;
    const int m = (int)(e >> 10);
    const int col = (int)(e & 1023);
    const int s = m >> 12, rm = m & 4095, n = rm >> 7, b = rm & 127;
    const float* src = x + (((size_t)((s * 128 + b) * 32 + n)) << 10) + col;
    const float4 v0 = *(const float4*)(src);
    const float4 v1 = *(const float4*)(src + 4);
    union { uint4 u; __half2 h[4]; } o;
    o.h[0] = __halves2half2(__float2half(v0.x), __float2half(v0.y));
    o.h[1] = __halves2half2(__float2half(v0.z), __float2half(v0.w));
    o.h[2] = __halves2half2(__float2half(v1.x), __float2half(v1.y));
    o.h[3] = __halves2half2(__float2half(v1.z), __float2half(v1.w));
    *(uint4*)(g_xa + e) = o.u;
}

// ---------------- prep: transpose W -> half ----------------
__global__ __launch_bounds__(256) void tsplit_kernel(
    const float* __restrict__ in, __half* __restrict__ oh, int R, int C)
{
    __shared__ float tile[32][33];
    const int r0 = blockIdx.y * 32, c0 = blockIdx.x * 32;
    const int tx = threadIdx.x, ty = threadIdx.y;
    #pragma unroll
    for (int j = ty; j < 32; j += 8)
        tile[j][tx] = in[(size_t)(r0 + j) * C + c0 + tx];
    __syncthreads();
    #pragma unroll
    for (int j = ty; j < 32; j += 8)
        oh[(size_t)(c0 + j) * R + r0 + tx] = __float2half(tile[tx][j]);
}

// ---------------- LayerNorm: half in, half out ----------------
__global__ __launch_bounds__(256) void ln_kernel(
    const float* __restrict__ gamma, const float* __restrict__ beta)
{
    const int r = blockIdx.x;
    const __half* xr = g_atth + (size_t)r * INNER_;
    const int tid = threadIdx.x;
    const int warp = tid >> 5, lane = tid & 31;

    float v[4];
    float sum = 0.f;
    #pragma unroll
    for (int i = 0; i < 4; i++) { v[i] = __half2float(xr[tid + i * 256]); sum += v[i]; }

    __shared__ float red[8];
    #pragma unroll
    for (int o = 16; o > 0; o >>= 1) sum += __shfl_xor_sync(0xffffffffu, sum, o);
    if (lane == 0) red[warp] = sum;
    __syncthreads();
    float tot = red[lane & 7];
    #pragma unroll
    for (int o = 4; o > 0; o >>= 1) tot += __shfl_xor_sync(0xffffffffu, tot, o);
    float mean = tot * (1.0f / 1024.0f);

    float sq = 0.f;
    #pragma unroll
    for (int i = 0; i < 4; i++) { float d = v[i] - mean; sq += d * d; }
    #pragma unroll
    for (int o = 16; o > 0; o >>= 1) sq += __shfl_xor_sync(0xffffffffu, sq, o);
    __syncthreads();
    if (lane == 0) red[warp] = sq;
    __syncthreads();
    float tot2 = red[lane & 7];
    #pragma unroll
    for (int o = 4; o > 0; o >>= 1) tot2 += __shfl_xor_sync(0xffffffffu, tot2, o);
    float var = tot2 * (1.0f / 1024.0f);
    float inv = rsqrtf(var + 1e-5f);

    #pragma unroll
    for (int i = 0; i < 4; i++) {
        int c = tid + i * 256;
        float yv = (v[i] - mean) * inv * gamma[c] + beta[c];
        g_yh[(size_t)r * INNER_ + c] = __float2half(yv);
    }
}

// ---------------- stream pack (static init; no device allocs) ----------------
struct StreamPack {
    cudaStream_t s1 = nullptr;
    cudaEvent_t eF = nullptr, eK = nullptr, e1 = nullptr, e2 = nullptr;
    bool ok = false;
    StreamPack() {
        ok = (cudaStreamCreateWithFlags(&s1, cudaStreamNonBlocking) == cudaSuccess) &&
             (cudaEventCreateWithFlags(&eF, cudaEventDisableTiming) == cudaSuccess) &&
             (cudaEventCreateWithFlags(&eK, cudaEventDisableTiming) == cudaSuccess) &&
             (cudaEventCreateWithFlags(&e1, cudaEventDisableTiming) == cudaSuccess) &&
             (cudaEventCreateWithFlags(&e2, cudaEventDisableTiming) == cudaSuccess);
    }
};
static StreamPack g_sp;

// ---------------- launch ----------------
extern "C" void kernel_launch(void* const* d_in, const int* in_sizes, int n_in,
                              void* d_out, int out_size)
{
    const float* x    = (const float*)d_in[0];
    const int*   mask = (const int*)  d_in[1];
    const float* q    = (const float*)d_in[2];
    const float* W_kv = (const float*)d_in[3];
    const float* ln_g = (const float*)d_in[4];
    const float* ln_b = (const float*)d_in[5];
    const float* W1   = (const float*)d_in[6];
    const float* b1   = (const float*)d_in[7];
    const float* W2   = (const float*)d_in[8];
    const float* b2   = (const float*)d_in[9];
    float* out = (float*)d_out;
    (void)in_sizes; (void)n_in; (void)out_size;

    __half *xa, *wkt, *w1t, *w2t, *yh, *hh;
    cudaGetSymbolAddress((void**)&xa,  g_xa);
    cudaGetSymbolAddress((void**)&wkt, g_wkt);
    cudaGetSymbolAddress((void**)&w1t, g_w1t);
    cudaGetSymbolAddress((void**)&w2t, g_w2t);
    cudaGetSymbolAddress((void**)&yh,  g_yh);
    cudaGetSymbolAddress((void**)&hh,  g_hh);

    cudaFuncSetAttribute(kv_attn_kernel, cudaFuncAttributeMaxDynamicSharedMemorySize, GEMM_SMEM);
    cudaFuncSetAttribute(mma_gemm_res,   cudaFuncAttributeMaxDynamicSharedMemorySize, GEMM_SMEM);
    cudaFuncSetAttribute(mma_gemm_geglu, cudaFuncAttributeMaxDynamicSharedMemorySize, GEGLU_SMEM);

    dim3 tb(32, 8);
    if (g_sp.ok) {
        cudaEventRecord(g_sp.eF, 0);
        cudaStreamWaitEvent(g_sp.s1, g_sp.eF, 0);
        tsplit_kernel<<<dim3(KVW_ / 32, D_ / 32), tb, 0, g_sp.s1>>>(W_kv, wkt, D_, KVW_);
        cudaEventRecord(g_sp.eK, g_sp.s1);
        tsplit_kernel<<<dim3(FF2_ / 32, INNER_ / 32), tb, 0, g_sp.s1>>>(W1, w1t, INNER_, FF2_);
        cudaEventRecord(g_sp.e1, g_sp.s1);
        tsplit_kernel<<<dim3(INNER_ / 32, FFH_ / 32), tb, 0, g_sp.s1>>>(W2, w2t, FFH_, INNER_);
        cudaEventRecord(g_sp.e2, g_sp.s1);

        prep_x_kernel<<<(KVROWS_ * (size_t)D_) / 8 / 256, 256>>>(x);
        cudaStreamWaitEvent(0, g_sp.eK, 0);
        kv_attn_kernel<<<256 * HEADS_, 256, GEMM_SMEM>>>(xa, wkt, q, mask);
        ln_kernel<<<ROWS_, 256>>>(ln_g, ln_b);
        cudaStreamWaitEvent(0, g_sp.e1, 0);
        mma_gemm_geglu<<<(ROWS_ / 128) * (FFH_ / 64), 256, GEGLU_SMEM>>>(yh, w1t, b1);
        cudaStreamWaitEvent(0, g_sp.e2, 0);
        mma_gemm_res<<<(ROWS_ / 128) * (INNER_ / 128), 256, GEMM_SMEM>>>(
            hh, w2t, out, INNER_, FFH_, b2, yh);
    } else {
        prep_x_kernel<<<(KVROWS_ * (size_t)D_) / 8 / 256, 256>>>(x);
        tsplit_kernel<<<dim3(KVW_ / 32, D_ / 32), tb>>>(W_kv, wkt, D_, KVW_);
        tsplit_kernel<<<dim3(FF2_ / 32, INNER_ / 32), tb>>>(W1, w1t, INNER_, FF2_);
        tsplit_kernel<<<dim3(INNER_ / 32, FFH_ / 32), tb>>>(W2, w2t, FFH_, INNER_);
        kv_attn_kernel<<<256 * HEADS_, 256, GEMM_SMEM>>>(xa, wkt, q, mask);
        ln_kernel<<<ROWS_, 256>>>(ln_g, ln_b);
        mma_gemm_geglu<<<(ROWS_ / 128) * (FFH_ / 64), 256, GEGLU_SMEM>>>(yh, w1t, b1);
        mma_gemm_res<<<(ROWS_ / 128) * (INNER_ / 128), 256, GEMM_SMEM>>>(
            hh, w2t, out, INNER_, FFH_, b2, yh);
    }
}